// round 5
// baseline (speedup 1.0000x reference)
#include <cuda_runtime.h>
#include <math.h>

#ifndef M_PI
#define M_PI 3.14159265358979323846
#endif

#define NBLK  148
#define NT    448
#define TXDIM 421
#define TYDIM 421
#define NRMAX 3
#define SRCI  210
#define SRCJ  210
#define RSLOT 4
#define SRCBUF 512

// Seq-stamped packets: 3 per direction per exchange (one exchange per 2 steps).
// g_pktU[k] : sent to bid+1 (block's TOP rows);  g_pktD[k] : sent to bid-1 (BOTTOM rows)
__device__ float4   g_pktU[3][RSLOT][NBLK][NT];
__device__ float4   g_pktD[3][RSLOT][NBLK][NT];
__device__ unsigned g_epochs[NBLK];   // per-block monotonic epoch (advances uniformly per launch)

static __device__ __forceinline__ void st_pkt(float4* p, float x, float y, float z, unsigned seq) {
    asm volatile("st.volatile.global.v4.f32 [%0], {%1,%2,%3,%4};"
                 :: "l"(p), "f"(x), "f"(y), "f"(z), "f"(__uint_as_float(seq)) : "memory");
}
static __device__ __forceinline__ float4 ld_pkt(const float4* p) {
    float4 v;
    asm volatile("ld.volatile.global.v4.f32 {%0,%1,%2,%3}, [%4];"
                 : "=f"(v.x), "=f"(v.y), "=f"(v.z), "=f"(v.w) : "l"(p) : "memory");
    return v;
}

__global__ void __launch_bounds__(NT, 1)
fdtd_mlor_kernel(const float* __restrict__ src, int src_len,
                 const float* __restrict__ C1a, const float* __restrict__ C2a,
                 const float* __restrict__ Cbdxa, const float* __restrict__ Cbdya,
                 const float* __restrict__ dbhxa, const float* __restrict__ dbhya,
                 const float* __restrict__ Caa, const float* __restrict__ Cba,
                 const float* __restrict__ Cca, const float* __restrict__ Cda,
                 const float* __restrict__ Cea,
                 const float* __restrict__ sig_ex, const float* __restrict__ sig_ey,
                 const float* __restrict__ sig_hx, const float* __restrict__ sig_hy,
                 const int* __restrict__ nsp,
                 float* __restrict__ out,
                 float kE, float kMu)
{
    const int bid = blockIdx.x;
    const int j   = threadIdx.x;

    const float ca   = Caa[0], cb = Cba[0], cc = Cca[0], cd = Cda[0], ce = Cea[0];
    const float C1   = C1a[0], C2 = C2a[0];
    const float Cbdx = Cbdxa[0], Cbdy = Cbdya[0];
    const float dbhx = dbhxa[0], dbhy = dbhya[0];

    int n = nsp ? nsp[0] : 200;
    if (n > src_len) n = src_len;
    if (n < 0) n = 0;
    const int npairs = n >> 1;
    const int rem    = n & 1;

    const int r0 = (bid * TXDIM) / NBLK;
    const int r1 = ((bid + 1) * TXDIM) / NBLK;
    const int nrows = r1 - r0;                 // 2 or 3
    const int gl0 = r0 - 1, gl1 = r0 - 2, gu0 = r1;  // ghost row indices
    const bool hasL = (bid > 0);
    const bool hasU = (bid < NBLK - 1);

    const bool colE = (j < TYDIM);
    const bool colH = (j < TYDIM - 1);

    float cEyE = 1.f, cEyMu = 1.f, cHyMu = 1.f;
    if (colE) { float s = sig_ey[j]; cEyE = expf(-s * kE); cEyMu = expf(-s * kMu); }
    if (colH) { cHyMu = expf(-sig_hy[j] * kMu); }

    float fDe[NRMAX], fHx[NRMAX], fHy[NRMAX];
    #pragma unroll
    for (int r = 0; r < NRMAX; ++r) {
        fDe[r] = 0.f; fHx[r] = 0.f; fHy[r] = 0.f;
        if (r < nrows) {
            int i = r0 + r;
            float sx = sig_ex[i];
            fDe[r] = expf(-sx * kE)  * cEyE;
            fHx[r] = expf(-sx * kMu) * cHyMu;
            fHy[r] = (i < TXDIM - 1) ? expf(-sig_hx[i] * kMu) * cEyMu : 0.f;
        }
    }
    // Ghost-row coefficients
    float fDeL0 = 0.f, fHxL0 = 0.f, fHyL0 = 0.f, fHyL1 = 0.f;
    float fDeU0 = 0.f, fHxU0 = 0.f, fHyU0 = 0.f;
    if (hasL) {
        float sx0 = sig_ex[gl0];
        fDeL0 = expf(-sx0 * kE)  * cEyE;
        fHxL0 = expf(-sx0 * kMu) * cHyMu;
        fHyL0 = expf(-sig_hx[gl0] * kMu) * cEyMu;
        fHyL1 = expf(-sig_hx[gl1] * kMu) * cEyMu;
    }
    if (hasU) {
        float sxu = sig_ex[gu0];
        fDeU0 = expf(-sxu * kE)  * cEyE;
        fHxU0 = expf(-sxu * kMu) * cHyMu;
        fHyU0 = expf(-sig_hx[gu0] * kMu) * cEyMu;
    }

    // Own rows: full state in registers
    float ez[NRMAX]   = {0.f, 0.f, 0.f};
    float eold[NRMAX] = {0.f, 0.f, 0.f};
    float jz[NRMAX]   = {0.f, 0.f, 0.f};
    float jold[NRMAX] = {0.f, 0.f, 0.f};
    float hx[NRMAX]   = {0.f, 0.f, 0.f};
    float hy[NRMAX]   = {0.f, 0.f, 0.f};
    // Ghost thread-local state
    float ghHyL1 = 0.f, ghHyL0 = 0.f, ghHyU0 = 0.f;
    float ghEoldL = 0.f, ghJzL = 0.f, ghJoldL = 0.f, ghHxL = 0.f;
    float ghEoldU = 0.f, ghJzU = 0.f, ghJoldU = 0.f, ghHxU = 0.f;

    __shared__ float sEz [NRMAX][NT + 4];   // own Ez rows (column exchange)
    __shared__ float sHx [NRMAX][NT + 4];   // own Hx rows
    __shared__ float sgEz[4][NT + 4];       // ghost Ez: 0=gl1 1=gl0 2=gu0 3=gu1
    __shared__ float sgHx[2][NT + 4];       // ghost Hx: 0=gl0 1=gu0
    __shared__ float sSrc[SRCBUF];

    #pragma unroll
    for (int r = 0; r < NRMAX; ++r) sEz[r][j] = 0.f;
    #pragma unroll
    for (int g = 0; g < 4; ++g) sgEz[g][j] = 0.f;
    if (j < 4) {
        #pragma unroll
        for (int r = 0; r < NRMAX; ++r) sEz[r][NT + j] = 0.f;
        #pragma unroll
        for (int g = 0; g < 4; ++g) sgEz[g][NT + j] = 0.f;
    }
    if (j < n && j < SRCBUF) sSrc[j] = src[j];

    const unsigned base = *(volatile unsigned*)&g_epochs[bid];

#define EUPDATE(r, hyBelow, tt)                                                    \
    do {                                                                           \
        int i_ = r0 + (r);                                                         \
        float eznew_ = 0.f;                                                        \
        if (i_ >= 1 && i_ <= TXDIM - 2 && j >= 1 && j <= TYDIM - 2) {              \
            float chy_ = hy[(r)] - (hyBelow);                                      \
            float chx_ = sHx[(r)][j] - sHx[(r)][j - 1];                            \
            float phi_ = (ca + 1.f) * jz[(r)] + cb * jold[(r)]                     \
                       + cd * ez[(r)] + ce * eold[(r)];                            \
            eznew_ = fDe[(r)] * (C1 * ez[(r)] + Cbdx * chy_ - Cbdy * chx_          \
                                 - C2 * phi_);                                     \
            if (i_ == SRCI && j == SRCJ)                                           \
                eznew_ += ((tt) < SRCBUF) ? sSrc[(tt)] : src[(tt)];                \
        }                                                                          \
        float jznew_ = ca * jz[(r)] + cb * jold[(r)] + cc * eznew_                 \
                     + cd * ez[(r)] + ce * eold[(r)];                              \
        jold[(r)] = jz[(r)]; jz[(r)] = jznew_;                                     \
        eold[(r)] = ez[(r)]; ez[(r)] = eznew_;                                     \
        sEz[(r)][j] = eznew_;                                                      \
    } while (0)

    // --- Poll + ingest ghosts for exchange e (wants seq base+e at slot (e-1)&3) ---
#define POLL_INGEST(e)                                                             \
    do {                                                                           \
        const int s_ = ((e) - 1) & (RSLOT - 1);                                   \
        const unsigned want_ = base + (unsigned)(e);                               \
        if (colE) {                                                                \
            if (hasL) {                                                            \
                const float4* p0 = &g_pktU[0][s_][bid - 1][j];                     \
                const float4* p1 = &g_pktU[1][s_][bid - 1][j];                     \
                const float4* p2 = &g_pktU[2][s_][bid - 1][j];                     \
                float4 v0 = ld_pkt(p0), v1 = ld_pkt(p1), v2 = ld_pkt(p2);          \
                while (__float_as_uint(v0.w) < want_) v0 = ld_pkt(p0);             \
                while (__float_as_uint(v1.w) < want_) v1 = ld_pkt(p1);             \
                while (__float_as_uint(v2.w) < want_) v2 = ld_pkt(p2);             \
                sgEz[1][j] = v0.x; sgEz[0][j] = v0.y; ghHyL0 = v0.z;               \
                ghHyL1 = v1.x; ghEoldL = v1.y; ghJzL = v1.z;                       \
                ghJoldL = v2.x; ghHxL = v2.y;                                      \
            }                                                                      \
            if (hasU) {                                                            \
                const float4* q0 = &g_pktD[0][s_][bid + 1][j];                     \
                const float4* q1 = &g_pktD[1][s_][bid + 1][j];                     \
                const float4* q2 = &g_pktD[2][s_][bid + 1][j];                     \
                float4 w0 = ld_pkt(q0), w1 = ld_pkt(q1), w2 = ld_pkt(q2);          \
                while (__float_as_uint(w0.w) < want_) w0 = ld_pkt(q0);             \
                while (__float_as_uint(w1.w) < want_) w1 = ld_pkt(q1);             \
                while (__float_as_uint(w2.w) < want_) w2 = ld_pkt(q2);             \
                sgEz[2][j] = w0.x; sgEz[3][j] = w0.y; ghHyU0 = w0.z;               \
                ghEoldU = w1.x; ghJzU = w1.y; ghJoldU = w1.z;                      \
                ghHxU = w2.x;                                                      \
            }                                                                      \
        }                                                                          \
    } while (0)

    // --- Step-A H phase: own + ghost H updates (inputs at level t) ---
#define STEPA_H()                                                                  \
    do {                                                                           \
        if (colE) {                                                                \
            if (colH) {                                                            \
                hx[0] = fHx[0] * (hx[0] - dbhx * (sEz[0][j + 1] - ez[0]));         \
                sHx[0][j] = hx[0];                                                 \
                hx[1] = fHx[1] * (hx[1] - dbhx * (sEz[1][j + 1] - ez[1]));         \
                sHx[1][j] = hx[1];                                                 \
                if (nrows == 3) {                                                  \
                    hx[2] = fHx[2] * (hx[2] - dbhx * (sEz[2][j + 1] - ez[2]));     \
                    sHx[2][j] = hx[2];                                             \
                }                                                                  \
            }                                                                      \
            hy[0] = fHy[0] * (hy[0] + dbhy * (((nrows >= 2) ? ez[1] : 0.f) - ez[0])); \
            if (nrows == 3) {                                                      \
                hy[1] = fHy[1] * (hy[1] + dbhy * (ez[2] - ez[1]));                 \
                hy[2] = fHy[2] * (hy[2] + dbhy * (sgEz[2][j] - ez[2]));            \
            } else {                                                               \
                hy[1] = fHy[1] * (hy[1] + dbhy * (sgEz[2][j] - ez[1]));            \
            }                                                                      \
            if (hasL) {                                                            \
                ghHyL1 = fHyL1 * (ghHyL1 + dbhy * (sgEz[1][j] - sgEz[0][j]));      \
                ghHyL0 = fHyL0 * (ghHyL0 + dbhy * (ez[0] - sgEz[1][j]));           \
                if (colH) {                                                        \
                    ghHxL = fHxL0 * (ghHxL - dbhx * (sgEz[1][j + 1] - sgEz[1][j]));\
                    sgHx[0][j] = ghHxL;                                            \
                }                                                                  \
            }                                                                      \
            if (hasU) {                                                            \
                ghHyU0 = fHyU0 * (ghHyU0 + dbhy * (sgEz[3][j] - sgEz[2][j]));      \
                if (colH) {                                                        \
                    ghHxU = fHxU0 * (ghHxU - dbhx * (sgEz[2][j + 1] - sgEz[2][j]));\
                    sgHx[1][j] = ghHxU;                                            \
                }                                                                  \
            }                                                                      \
        }                                                                          \
    } while (0)

    // --- Step-A E phase: own rows + ghost Ez at gl0/gu0 (advance to t+1) ---
#define STEPA_E(tt)                                                                \
    do {                                                                           \
        if (colE) {                                                                \
            EUPDATE(0, ghHyL0, (tt));                                              \
            EUPDATE(1, hy[0], (tt));                                               \
            if (nrows == 3) EUPDATE(2, hy[1], (tt));                               \
            if (hasL && j >= 1 && j <= TYDIM - 2) {                                \
                float ezt_ = sgEz[1][j];                                           \
                float chy_ = ghHyL0 - ghHyL1;                                      \
                float chx_ = sgHx[0][j] - sgHx[0][j - 1];                          \
                float phi_ = (ca + 1.f) * ghJzL + cb * ghJoldL                     \
                           + cd * ezt_ + ce * ghEoldL;                             \
                float ezn_ = fDeL0 * (C1 * ezt_ + Cbdx * chy_ - Cbdy * chx_        \
                                      - C2 * phi_);                               \
                if (gl0 == SRCI && j == SRCJ)                                      \
                    ezn_ += ((tt) < SRCBUF) ? sSrc[(tt)] : src[(tt)];              \
                sgEz[1][j] = ezn_;                                                 \
            }                                                                      \
            if (hasU && j >= 1 && j <= TYDIM - 2) {                                \
                float ezt_ = sgEz[2][j];                                           \
                float hyTopOwn_ = (nrows == 3) ? hy[2] : hy[1];                    \
                float chy_ = ghHyU0 - hyTopOwn_;                                   \
                float chx_ = sgHx[1][j] - sgHx[1][j - 1];                          \
                float phi_ = (ca + 1.f) * ghJzU + cb * ghJoldU                     \
                           + cd * ezt_ + ce * ghEoldU;                             \
                float ezn_ = fDeU0 * (C1 * ezt_ + Cbdx * chy_ - Cbdy * chx_        \
                                      - C2 * phi_);                               \
                if (gu0 == SRCI && j == SRCJ)                                      \
                    ezn_ += ((tt) < SRCBUF) ? sSrc[(tt)] : src[(tt)];              \
                sgEz[2][j] = ezn_;                                                 \
            }                                                                      \
        }                                                                          \
    } while (0)

    __syncthreads();   // zeros + sSrc visible

    for (int p = 0; p < npairs; ++p) {
        const int tA = 2 * p;

        if (p > 0) POLL_INGEST(p);
        __syncthreads();                 // BAR(a): sEz (prev E-phase) + sgEz ingested

        STEPA_H();
        __syncthreads();                 // BAR(b): sHx/sgHx ready

        STEPA_E(tA);
        __syncthreads();                 // BAR(c): sEz/sgEz at t+1 ready

        // ---- Step B H phase (inputs at t+1) ----
        if (colE) {
            if (colH) {
                hx[0] = fHx[0] * (hx[0] - dbhx * (sEz[0][j + 1] - ez[0]));
                sHx[0][j] = hx[0];
                hx[1] = fHx[1] * (hx[1] - dbhx * (sEz[1][j + 1] - ez[1]));
                sHx[1][j] = hx[1];
                if (nrows == 3) {
                    hx[2] = fHx[2] * (hx[2] - dbhx * (sEz[2][j + 1] - ez[2]));
                    sHx[2][j] = hx[2];
                }
            }
            hy[0] = fHy[0] * (hy[0] + dbhy * (ez[1] - ez[0]));
            if (nrows == 3) {
                hy[1] = fHy[1] * (hy[1] + dbhy * (ez[2] - ez[1]));
                hy[2] = fHy[2] * (hy[2] + dbhy * (sgEz[2][j] - ez[2]));
            } else {
                hy[1] = fHy[1] * (hy[1] + dbhy * (sgEz[2][j] - ez[1]));
            }
            if (hasL)
                ghHyL0 = fHyL0 * (ghHyL0 + dbhy * (ez[0] - sgEz[1][j]));
        }
        __syncthreads();                 // BAR(d): sHx at t+2-inputs ready

        // ---- Step B E phase (advance to t+2) + publish ----
        const int tB = tA + 1;
        const int s = p & (RSLOT - 1);
        const unsigned seq = base + (unsigned)p + 1u;
        if (colE) {
            EUPDATE(0, ghHyL0, tB);
            EUPDATE(1, hy[0], tB);
            if (nrows == 3) {
                EUPDATE(2, hy[1], tB);
                st_pkt(&g_pktU[0][s][bid][j], ez[2], ez[1], hy[2], seq);
                st_pkt(&g_pktU[1][s][bid][j], hy[1], eold[2], jz[2], seq);
                st_pkt(&g_pktU[2][s][bid][j], jold[2], hx[2], 0.f, seq);
            } else {
                st_pkt(&g_pktU[0][s][bid][j], ez[1], ez[0], hy[1], seq);
                st_pkt(&g_pktU[1][s][bid][j], hy[0], eold[1], jz[1], seq);
                st_pkt(&g_pktU[2][s][bid][j], jold[1], hx[1], 0.f, seq);
            }
            st_pkt(&g_pktD[0][s][bid][j], ez[0], ez[1], hy[0], seq);
            st_pkt(&g_pktD[1][s][bid][j], eold[0], jz[0], jold[0], seq);
            st_pkt(&g_pktD[2][s][bid][j], hx[0], 0.f, 0.f, seq);
        }
        // loop: next iteration's POLL/sgEz writes are own-column; cross-column
        // reads only occur after BAR(a)
    }

    // ---- Odd tail step ----
    if (rem) {
        if (npairs > 0) POLL_INGEST(npairs);
        __syncthreads();
        STEPA_H();
        __syncthreads();
        const int tT = 2 * npairs;
        if (colE) {
            EUPDATE(0, ghHyL0, tT);
            EUPDATE(1, hy[0], tT);
            if (nrows == 3) EUPDATE(2, hy[1], tT);
        }
    }

    #pragma unroll
    for (int r = 0; r < NRMAX; ++r) {
        if (r < nrows && colE) out[(r0 + r) * TYDIM + j] = ez[r];
    }

    if (j == 0) *(volatile unsigned*)&g_epochs[bid] = base + (unsigned)npairs;

#undef EUPDATE
#undef POLL_INGEST
#undef STEPA_H
#undef STEPA_E
}

extern "C" void kernel_launch(void* const* d_in, const int* in_sizes, int n_in,
                              void* d_out, int out_size) {
    const float* src    = (const float*)d_in[0];
    const float* C1a    = (const float*)d_in[1];
    const float* C2a    = (const float*)d_in[2];
    const float* Cbdxa  = (const float*)d_in[3];
    const float* Cbdya  = (const float*)d_in[4];
    const float* dbhxa  = (const float*)d_in[5];
    const float* dbhya  = (const float*)d_in[6];
    const float* Caa    = (const float*)d_in[7];
    const float* Cba    = (const float*)d_in[8];
    const float* Cca    = (const float*)d_in[9];
    const float* Cda    = (const float*)d_in[10];
    const float* Cea    = (const float*)d_in[11];
    const float* sigex  = (const float*)d_in[12];
    const float* sigey  = (const float*)d_in[13];
    const float* sighx  = (const float*)d_in[14];
    const float* sighy  = (const float*)d_in[15];
    const int*   nsp    = (n_in >= 17) ? (const int*)d_in[16] : nullptr;

    const double EPS0 = 1e-9 / 36.0 / M_PI;
    const double MU0  = 4.0 * M_PI * 1e-7;
    const double C0   = 1.0 / sqrt(MU0 * EPS0);
    const double DX = 2.5e-8, DY = 2.5e-8;
    const double DT = 0.99 / C0 / sqrt(1.0 / (DX * DX) + 1.0 / (DY * DY));
    const float kE  = (float)(DT / EPS0);
    const float kMu = (float)(DT / MU0);

    fdtd_mlor_kernel<<<NBLK, NT>>>(src, in_sizes[0],
                                   C1a, C2a, Cbdxa, Cbdya, dbhxa, dbhya,
                                   Caa, Cba, Cca, Cda, Cea,
                                   sigex, sigey, sighx, sighy,
                                   nsp, (float*)d_out, kE, kMu);
    (void)out_size;
}

// round 6
// speedup vs baseline: 1.3953x; 1.3953x over previous
#include <cuda_runtime.h>
#include <math.h>

#ifndef M_PI
#define M_PI 3.14159265358979323846
#endif

#define NBLK  148
#define NT    448
#define TXDIM 421
#define TYDIM 421
#define NRMAX 3
#define SRCI  210
#define SRCJ  210
#define RSLOT 4
#define SRCBUF 512

// Flag+data packets (flag rides with data in one 16B sector):
//  pktT: {ez_row_first, 0, _, seq} — consumed by bid-1 as ezBot
//  pktB: {ez_row_last, hy_row_last, _, seq} — consumed by bid+1 as ezTop/hyTop
__device__ float4   g_pktT[RSLOT][NBLK][NT];
__device__ float4   g_pktB[RSLOT][NBLK][NT];
__device__ unsigned g_epoch;   // monotonic across graph replays

static __device__ __forceinline__ void st_pkt(float4* p, float x, float y, unsigned seq) {
    asm volatile("st.volatile.global.v4.f32 [%0], {%1,%2,%3,%4};"
                 :: "l"(p), "f"(x), "f"(y), "f"(0.f), "f"(__uint_as_float(seq)) : "memory");
}
static __device__ __forceinline__ float4 ld_pkt(const float4* p) {
    float4 v;
    asm volatile("ld.volatile.global.v4.f32 {%0,%1,%2,%3}, [%4];"
                 : "=f"(v.x), "=f"(v.y), "=f"(v.z), "=f"(v.w) : "l"(p) : "memory");
    return v;
}

__global__ void __launch_bounds__(NT, 1)
fdtd_mlor_kernel(const float* __restrict__ src, int src_len,
                 const float* __restrict__ C1a, const float* __restrict__ C2a,
                 const float* __restrict__ Cbdxa, const float* __restrict__ Cbdya,
                 const float* __restrict__ dbhxa, const float* __restrict__ dbhya,
                 const float* __restrict__ Caa, const float* __restrict__ Cba,
                 const float* __restrict__ Cca, const float* __restrict__ Cda,
                 const float* __restrict__ Cea,
                 const float* __restrict__ sig_ex, const float* __restrict__ sig_ey,
                 const float* __restrict__ sig_hx, const float* __restrict__ sig_hy,
                 const int* __restrict__ nsp,
                 float* __restrict__ out,
                 float kE, float kMu)
{
    const int bid = blockIdx.x;
    const int j   = threadIdx.x;

    const float ca   = Caa[0], cb = Cba[0], cc = Cca[0], cd = Cda[0], ce = Cea[0];
    const float C1   = C1a[0], C2 = C2a[0];
    const float Cbdx = Cbdxa[0], Cbdy = Cbdya[0];
    const float dbhx = dbhxa[0], dbhy = dbhya[0];

    int n = nsp ? nsp[0] : 200;
    if (n > src_len) n = src_len;
    if (n < 0) n = 0;

    const int r0 = (bid * TXDIM) / NBLK;
    const int r1 = ((bid + 1) * TXDIM) / NBLK;
    const int nrows = r1 - r0;                 // 2 or 3

    const bool colE = (j < TYDIM);             // valid Ez/Hy column
    const bool colH = (j < TYDIM - 1);         // Hx(.,j) exists
    const bool colM = (j >= 1 && j < TYDIM);   // Hx(.,j-1) exists

    // Column decay factors
    float cEyE = 1.f, cEyMu = 1.f, cHyMu = 1.f, cHyMuM = 1.f;
    if (colE) { float s = sig_ey[j]; cEyE = expf(-s * kE); cEyMu = expf(-s * kMu); }
    if (colH) cHyMu  = expf(-sig_hy[j]     * kMu);
    if (colM) cHyMuM = expf(-sig_hy[j - 1] * kMu);

    float fDe[NRMAX], fHx[NRMAX], fHxm[NRMAX], fHy[NRMAX];
    #pragma unroll
    for (int r = 0; r < NRMAX; ++r) {
        fDe[r] = 0.f; fHx[r] = 0.f; fHxm[r] = 0.f; fHy[r] = 0.f;
        if (r < nrows) {
            int i = r0 + r;
            float sx  = sig_ex[i];
            float rMu = expf(-sx * kMu);
            fDe[r]  = expf(-sx * kE) * cEyE;
            fHx[r]  = rMu * cHyMu;
            fHxm[r] = rMu * cHyMuM;
            fHy[r]  = (i < TXDIM - 1) ? expf(-sig_hx[i] * kMu) * cEyMu : 0.f;
        }
    }
    const float fHyHalo = (r0 > 0) ? expf(-sig_hx[r0 - 1] * kMu) * cEyMu : 0.f;

    // All state in registers
    float ez[NRMAX]   = {0.f, 0.f, 0.f};
    float eold[NRMAX] = {0.f, 0.f, 0.f};
    float jz[NRMAX]   = {0.f, 0.f, 0.f};
    float jold[NRMAX] = {0.f, 0.f, 0.f};
    float hx[NRMAX]   = {0.f, 0.f, 0.f};   // Hx(i, j)
    float hxm[NRMAX]  = {0.f, 0.f, 0.f};   // Hx(i, j-1)
    float hy[NRMAX]   = {0.f, 0.f, 0.f};

    __shared__ float sEz[2][NRMAX][NT + 4];  // ping-pong Ez rows (j±1 exchange)
    __shared__ float sSrc[SRCBUF];

    #pragma unroll
    for (int r = 0; r < NRMAX; ++r) { sEz[0][r][j] = 0.f; }
    if (j < 4) {
        #pragma unroll
        for (int r = 0; r < NRMAX; ++r) { sEz[0][r][NT + j] = 0.f; sEz[1][r][NT + j] = 0.f; }
    }
    if (j < n && j < SRCBUF) sSrc[j] = src[j];

    const unsigned base = *(volatile unsigned*)&g_epoch;

#define EUPDATE(r, hyBelow)                                                        \
    do {                                                                           \
        int i_ = r0 + (r);                                                         \
        float eznew_ = 0.f;                                                        \
        if (i_ >= 1 && i_ <= TXDIM - 2 && j >= 1 && j <= TYDIM - 2) {              \
            float chy_ = hy[(r)] - (hyBelow);                                      \
            float chx_ = hx[(r)] - hxm[(r)];                                       \
            eznew_ = fDe[(r)] * (C1 * ez[(r)] + Cbdx * chy_ - Cbdy * chx_          \
                                 - C2 * phi[(r)]);                                 \
            if (i_ == SRCI && j == SRCJ)                                           \
                eznew_ += (t < SRCBUF) ? sSrc[t] : src[t];                         \
        }                                                                          \
        jold[(r)] = jz[(r)]; jz[(r)] = jpart[(r)] + cc * eznew_;                   \
        eold[(r)] = ez[(r)]; ez[(r)] = eznew_;                                     \
        sEz[nxt][(r)][j] = eznew_;                                                 \
    } while (0)

    __syncthreads();   // zeros + sSrc visible

    for (int t = 0; t < n; ++t) {
        const int cur = t & 1, nxt = cur ^ 1;
        const int sp = (t + RSLOT - 1) & (RSLOT - 1);
        const unsigned want = base + (unsigned)t;

        const bool needB = (t > 0) && (bid > 0)        && colE;
        const bool needT = (t > 0) && (bid < NBLK - 1) && colE;
        const float4* pB = &g_pktB[sp][bid - 1][j];
        const float4* pT = &g_pktT[sp][bid + 1][j];

        // Optimistic poll — RT hides under the local compute below
        float4 vB = make_float4(0.f, 0.f, 0.f, 0.f);
        float4 vT = make_float4(0.f, 0.f, 0.f, 0.f);
        if (needB) vB = ld_pkt(pB);
        if (needT) vT = ld_pkt(pT);

        // ---- Local H compute + J/E polynomial precompute (no halo needed) ----
        float phi[NRMAX], jpart[NRMAX];
        if (colE) {
            #pragma unroll
            for (int r = 0; r < NRMAX; ++r) {
                if (r < nrows) {
                    if (colH)
                        hx[r]  = fHx[r]  * (hx[r]  - dbhx * (sEz[cur][r][j + 1] - ez[r]));
                    if (colM)
                        hxm[r] = fHxm[r] * (hxm[r] - dbhx * (ez[r] - sEz[cur][r][j - 1]));
                    if (r + 1 < nrows)
                        hy[r] = fHy[r] * (hy[r] + dbhy * (ez[r + 1] - ez[r]));
                    float jp = ca * jz[r] + cb * jold[r] + cd * ez[r] + ce * eold[r];
                    jpart[r] = jp;
                    phi[r]   = jp + jz[r];
                }
            }
        }

        // ---- Complete polls (flag+data in one packet) ----
        float ezTop = 0.f, hyTop = 0.f, ezBot = 0.f;
        if (needB) {
            while (__float_as_uint(vB.w) < want) vB = ld_pkt(pB);
            ezTop = vB.x; hyTop = vB.y;
        }
        if (needT) {
            while (__float_as_uint(vT.w) < want) vT = ld_pkt(pT);
            ezBot = vT.x;
        }

        // ---- Boundary H (needs halo) ----
        float hyPrev = 0.f;
        if (colE) {
            if (nrows == 3) hy[2] = fHy[2] * (hy[2] + dbhy * (ezBot - ez[2]));
            else            hy[1] = fHy[1] * (hy[1] + dbhy * (ezBot - ez[1]));
            if (bid > 0)
                hyPrev = fHyHalo * (hyTop + dbhy * (ez[0] - ezTop));
        }

        // ---- E + J update; publish boundary packets ASAP (no shared reads here) ----
        const int s = t & (RSLOT - 1);
        const unsigned seq = base + (unsigned)t + 1u;
        if (colE) {
            EUPDATE(0, hyPrev);
            st_pkt(&g_pktT[s][bid][j], ez[0], 0.f, seq);
            if (nrows == 3) {
                EUPDATE(2, hy[1]);
                st_pkt(&g_pktB[s][bid][j], ez[2], hy[2], seq);
                EUPDATE(1, hy[0]);          // interior row after publishes
            } else {
                EUPDATE(1, hy[0]);
                st_pkt(&g_pktB[s][bid][j], ez[1], hy[1], seq);
            }
        }

        __syncthreads();   // single barrier: sEz[nxt] complete before next H phase
    }
#undef EUPDATE

    #pragma unroll
    for (int r = 0; r < NRMAX; ++r) {
        if (r < nrows && colE) out[(r0 + r) * TYDIM + j] = ez[r];
    }

    // Advance epoch for the next graph replay (same value from every block)
    if (j == 0) *(volatile unsigned*)&g_epoch = base + (unsigned)n;
}

extern "C" void kernel_launch(void* const* d_in, const int* in_sizes, int n_in,
                              void* d_out, int out_size) {
    const float* src    = (const float*)d_in[0];
    const float* C1a    = (const float*)d_in[1];
    const float* C2a    = (const float*)d_in[2];
    const float* Cbdxa  = (const float*)d_in[3];
    const float* Cbdya  = (const float*)d_in[4];
    const float* dbhxa  = (const float*)d_in[5];
    const float* dbhya  = (const float*)d_in[6];
    const float* Caa    = (const float*)d_in[7];
    const float* Cba    = (const float*)d_in[8];
    const float* Cca    = (const float*)d_in[9];
    const float* Cda    = (const float*)d_in[10];
    const float* Cea    = (const float*)d_in[11];
    const float* sigex  = (const float*)d_in[12];
    const float* sigey  = (const float*)d_in[13];
    const float* sighx  = (const float*)d_in[14];
    const float* sighy  = (const float*)d_in[15];
    const int*   nsp    = (n_in >= 17) ? (const int*)d_in[16] : nullptr;

    const double EPS0 = 1e-9 / 36.0 / M_PI;
    const double MU0  = 4.0 * M_PI * 1e-7;
    const double C0   = 1.0 / sqrt(MU0 * EPS0);
    const double DX = 2.5e-8, DY = 2.5e-8;
    const double DT = 0.99 / C0 / sqrt(1.0 / (DX * DX) + 1.0 / (DY * DY));
    const float kE  = (float)(DT / EPS0);
    const float kMu = (float)(DT / MU0);

    fdtd_mlor_kernel<<<NBLK, NT>>>(src, in_sizes[0],
                                   C1a, C2a, Cbdxa, Cbdya, dbhxa, dbhya,
                                   Caa, Cba, Cca, Cda, Cea,
                                   sigex, sigey, sighx, sighy,
                                   nsp, (float*)d_out, kE, kMu);
    (void)out_size;
}